// round 8
// baseline (speedup 1.0000x reference)
#include <cuda_runtime.h>

// CellListComputer: cell-list build, 100k atoms, 20^3 buckets, sm_103a.
// Output layout (float32): [pairs_u | pairs_l | lower_between | frac | imidx | atidx]
// 4 launches:
//   k_init   : zero bucket counters + params
//   k_bucket : bucketize + per-bucket atomic counts; last block: u64 scan -> cum,poff,P
//   k_place  : placement via atomicAdd + per-atom neighbor-total scan; last: L,F
//   k_emit   : [bucket warps: build seq once -> replicate to atoms, sort -> imidx/atidx,
//               pairs] [frac]

#define MAXN   100000
#define MAXB   8192
#define MAXCH  104
#define SEQCAP 192     // per-warp staged sequence capacity (T ~ 87 expected, max ~140)
#define ATCAP  64      // per-warp staged atom capacity (count ~ 12 expected, max ~30)

__device__ int g_grid[3];
__device__ int g_scal[3];
__device__ int g_B;
__device__ int g_P;
__device__ int g_L;
__device__ int g_F;          // 2*P + L (start of frac section)
__device__ unsigned g_done1, g_done2;

__device__ __align__(16) int g_counts[MAXB];
__device__ __align__(16) int g_fill[MAXB];
__device__ __align__(16) int g_cum[MAXB];
__device__ __align__(16) int g_poff[MAXB];
__device__ int g_vec[MAXN];          // packed vx | vy<<8 | vz<<16
__device__ int g_tmp[MAXN];          // unordered bucket-sliced atom indices
__device__ int g_aoffL[MAXN];        // block-local exclusive prefix of per-atom totals
__device__ int g_bsum[MAXCH];
__device__ int g_bpre[MAXCH];

// inclusive block scan (int), blockDim.x == 1024
__device__ __forceinline__ int blkscan1024(int v, int* wsum) {
    int t = threadIdx.x, lane = t & 31, w = t >> 5;
    #pragma unroll
    for (int o = 1; o < 32; o <<= 1) {
        int x = __shfl_up_sync(0xffffffffu, v, o);
        if (lane >= o) v += x;
    }
    if (lane == 31) wsum[w] = v;
    __syncthreads();
    if (w == 0) {
        int s = wsum[lane];
        #pragma unroll
        for (int o = 1; o < 32; o <<= 1) {
            int x = __shfl_up_sync(0xffffffffu, s, o);
            if (lane >= o) s += x;
        }
        wsum[lane] = s;
    }
    __syncthreads();
    return v + ((w > 0) ? wsum[w - 1] : 0);
}

// inclusive block scan (u64 packed), blockDim.x == 1024
__device__ __forceinline__ unsigned long long
blkscan1024_u64(unsigned long long v, unsigned long long* wsum) {
    int t = threadIdx.x, lane = t & 31, w = t >> 5;
    #pragma unroll
    for (int o = 1; o < 32; o <<= 1) {
        unsigned long long x = __shfl_up_sync(0xffffffffu, v, o);
        if (lane >= o) v += x;
    }
    if (lane == 31) wsum[w] = v;
    __syncthreads();
    if (w == 0) {
        unsigned long long s = wsum[lane];
        #pragma unroll
        for (int o = 1; o < 32; o <<= 1) {
            unsigned long long x = __shfl_up_sync(0xffffffffu, s, o);
            if (lane >= o) s += x;
        }
        wsum[lane] = s;
    }
    __syncthreads();
    return v + ((w > 0) ? wsum[w - 1] : 0ull);
}

__global__ void k_init(const float* __restrict__ cell) {
    int t = threadIdx.x;
    if (t == 0) {
        float bl = (float)(5.2 / 1.0 + 1e-5);
        int g0 = (int)floorf(cell[0] / bl) + 1;
        int g1 = (int)floorf(cell[4] / bl) + 1;
        int g2 = (int)floorf(cell[8] / bl) + 1;
        g_grid[0] = g0; g_grid[1] = g1; g_grid[2] = g2;
        g_B = g0 * g1 * g2;
        g_scal[0] = g1 * g2; g_scal[1] = g1; g_scal[2] = 1;
        g_done1 = 0; g_done2 = 0;
    }
    #pragma unroll
    for (int j = 0; j < MAXB / 1024; ++j) {
        g_counts[j * 1024 + t] = 0;
        g_fill[j * 1024 + t] = 0;
    }
}

// bucketize + count; last-arriving block scans buckets -> g_cum, g_poff, g_P
__global__ void k_bucket(const float* __restrict__ coord,
                         const float* __restrict__ cell, int n) {
    int i = blockIdx.x * 1024 + threadIdx.x;
    if (i < n) {
        float d0 = __ldg(cell + 0), d1 = __ldg(cell + 4), d2 = __ldg(cell + 8);
        float fx = __ldg(coord + 3 * i + 0) / d0;
        float fy = __ldg(coord + 3 * i + 1) / d1;
        float fz = __ldg(coord + 3 * i + 2) / d2;
        int vx = __float2int_rn(fx * (float)(g_grid[0] - 1));
        int vy = __float2int_rn(fy * (float)(g_grid[1] - 1));
        int vz = __float2int_rn(fz * (float)(g_grid[2] - 1));
        int flat = vx * g_scal[0] + vy * g_scal[1] + vz * g_scal[2];
        g_vec[i] = vx | (vy << 8) | (vz << 16);
        atomicAdd(&g_counts[flat], 1);
    }
    __threadfence();
    __syncthreads();
    __shared__ int lastflag;
    if (threadIdx.x == 0)
        lastflag = (atomicAdd(&g_done1, 1) == gridDim.x - 1);
    __syncthreads();
    if (!lastflag) return;

    // ---- bucket scan: counts + pair-counts packed in u64, 8 buckets/thread ----
    __shared__ unsigned long long ws64[32];
    int t = threadIdx.x;
    int cc[8], eC[8], eP[8];
    #pragma unroll
    for (int j = 0; j < 8; ++j) cc[j] = __ldcg(&g_counts[t * 8 + j]);
    int sC = 0, sP = 0;
    #pragma unroll
    for (int j = 0; j < 8; ++j) {
        eC[j] = sC; sC += cc[j];
        eP[j] = sP; sP += cc[j] * (cc[j] - 1) / 2;
    }
    unsigned long long v = ((unsigned long long)(unsigned)sC << 32) | (unsigned)sP;
    unsigned long long incl = blkscan1024_u64(v, ws64);
    unsigned long long excl = incl - v;
    int baseC = (int)(excl >> 32);
    int baseP = (int)(excl & 0xffffffffull);
    int4 oc0 = make_int4(baseC + eC[0], baseC + eC[1], baseC + eC[2], baseC + eC[3]);
    int4 oc1 = make_int4(baseC + eC[4], baseC + eC[5], baseC + eC[6], baseC + eC[7]);
    int4 op0 = make_int4(baseP + eP[0], baseP + eP[1], baseP + eP[2], baseP + eP[3]);
    int4 op1 = make_int4(baseP + eP[4], baseP + eP[5], baseP + eP[6], baseP + eP[7]);
    *reinterpret_cast<int4*>(&g_cum[t * 8])      = oc0;
    *reinterpret_cast<int4*>(&g_cum[t * 8 + 4])  = oc1;
    *reinterpret_cast<int4*>(&g_poff[t * 8])     = op0;
    *reinterpret_cast<int4*>(&g_poff[t * 8 + 4]) = op1;
    if (t == 1023) g_P = (int)(incl & 0xffffffffull);
}

// unordered placement + per-atom neighbor totals; last block: L, F, bpre
__global__ void k_place(int n, int nch) {
    __shared__ int ws[32];
    int t = threadIdx.x;
    int i = blockIdx.x * 1024 + t;
    bool valid = (i < n);
    int tsum = 0;
    if (valid) {
        int pk = g_vec[i];
        int vx = pk & 0xFF, vy = (pk >> 8) & 0xFF, vz = (pk >> 16) & 0xFF;
        int g0 = g_grid[0], g1 = g_grid[1], g2 = g_grid[2];
        int s0 = g_scal[0], s1 = g_scal[1];
        int flat = vx * s0 + vy * s1 + vz;
        int slot = g_cum[flat] + atomicAdd(&g_fill[flat], 1);
        g_tmp[slot] = i;
        #pragma unroll
        for (int d = 0; d < 7; ++d) {
            int dx = (d >> 2) - 1;
            int dy = ((d >> 1) & 1) - 1;
            int dz = (d & 1) - 1;
            int nx = vx + dx; if (nx < 0) nx += g0;
            int ny = vy + dy; if (ny < 0) ny += g1;
            int nz = vz + dz; if (nz < 0) nz += g2;
            tsum += g_counts[nx * s0 + ny * s1 + nz];
        }
    }
    int incl = blkscan1024(tsum, ws);
    if (valid) g_aoffL[i] = incl - tsum;
    if (t == 1023) g_bsum[blockIdx.x] = incl;

    __threadfence();
    __syncthreads();
    __shared__ int lastflag;
    if (t == 0) lastflag = (atomicAdd(&g_done2, 1) == gridDim.x - 1);
    __syncthreads();
    if (!lastflag) return;

    if (t < 32) {
        int ex[4];
        int s = 0;
        #pragma unroll
        for (int j = 0; j < 4; ++j) {
            int idx = t * 4 + j;
            int x = (idx < nch) ? __ldcg(&g_bsum[idx]) : 0;
            ex[j] = s; s += x;
        }
        int iw = s;
        #pragma unroll
        for (int o = 1; o < 32; o <<= 1) {
            int x = __shfl_up_sync(0xffffffffu, iw, o);
            if (t >= o) iw += x;
        }
        int base = iw - s;
        #pragma unroll
        for (int j = 0; j < 4; ++j) {
            int idx = t * 4 + j;
            if (idx < nch) g_bpre[idx] = base + ex[j];
        }
        if (t == 31) { g_L = iw; g_F = 2 * g_P + iw; }
    }
}

// Fused output writer. [0,bktb): warp per bucket (seq+fill+sort+pairs); rest: frac.
__global__ void k_emit(float* __restrict__ out,
                       const float* __restrict__ coord,
                       const float* __restrict__ cell,
                       int n, int bktb) {
    int blk = blockIdx.x;
    int t = threadIdx.x;
    if (blk < bktb) {
        const unsigned FULL = 0xffffffffu;
        __shared__ float s_seq[32][SEQCAP];
        __shared__ int   s_atom[32][ATCAP];
        __shared__ int   s_base[32][ATCAP];
        int wib = t >> 5, lane = t & 31;
        int bkt = blk * 32 + wib;
        if (bkt >= g_B) return;
        int c = g_counts[bkt];
        if (c == 0) return;
        int cum = g_cum[bkt];
        int P = g_P;

        // ---- per-bucket neighbor segment table ----
        int cnt_d = 0, cum_d = 0;
        if (lane < 7) {
            int s0 = g_scal[0], s1g = g_scal[1];
            int g0 = g_grid[0], g1 = g_grid[1], g2 = g_grid[2];
            int vx = bkt / s0; int r = bkt - vx * s0;
            int vy = r / s1g;  int vz = r - vy * s1g;
            int dx = (lane >> 2) - 1;
            int dy = ((lane >> 1) & 1) - 1;
            int dz = (lane & 1) - 1;
            int nx = vx + dx; if (nx < 0) nx += g0;
            int ny = vy + dy; if (ny < 0) ny += g1;
            int nz = vz + dz; if (nz < 0) nz += g2;
            int nb = nx * s0 + ny * s1g + nz;
            cnt_d = g_counts[nb];
            cum_d = g_cum[nb];
        }
        int sc = cnt_d;
        #pragma unroll
        for (int o = 1; o < 8; o <<= 1) {
            int x = __shfl_up_sync(FULL, sc, o);
            if (lane >= o) sc += x;
        }
        int st = sc - cnt_d;
        float fseg = (float)(cum_d - st);
        int T = __shfl_sync(FULL, sc, 6);

        float f0 = __shfl_sync(FULL, fseg, 0);
        int   s1 = __shfl_sync(FULL, st, 1); float f1 = __shfl_sync(FULL, fseg, 1);
        int   s2 = __shfl_sync(FULL, st, 2); float f2 = __shfl_sync(FULL, fseg, 2);
        int   s3 = __shfl_sync(FULL, st, 3); float f3 = __shfl_sync(FULL, fseg, 3);
        int   s4 = __shfl_sync(FULL, st, 4); float f4 = __shfl_sync(FULL, fseg, 4);
        int   s5 = __shfl_sync(FULL, st, 5); float f5 = __shfl_sync(FULL, fseg, 5);
        int   s6 = __shfl_sync(FULL, st, 6); float f6 = __shfl_sync(FULL, fseg, 6);

        // ---- build sequence once into smem ----
        int tcap = (T < SEQCAP) ? T : SEQCAP;
        {
            float kf = (float)lane;
            for (int k = lane; k < tcap; k += 32, kf += 32.0f) {
                float s = f0;
                if (k >= s1) s = f1;
                if (k >= s2) s = f2;
                if (k >= s3) s = f3;
                if (k >= s4) s = f4;
                if (k >= s5) s = f5;
                if (k >= s6) s = f6;
                s_seq[wib][k] = s + kf;
            }
        }

        // ---- stage atoms + absolute bases ----
        int twoP = 2 * P;
        for (int j = lane; j < c && j < ATCAP; j += 32) {
            int a = g_tmp[cum + j];
            s_atom[wib][j] = a;
            s_base[wib][j] = twoP + g_aoffL[a] + g_bpre[a >> 10];
        }
        __syncwarp();

        // ---- replicate sequence to each atom's slice ----
        for (int j = 0; j < c; ++j) {
            int base;
            if (j < ATCAP) base = s_base[wib][j];
            else {
                int a = 0;
                if (lane == 0) a = __ldg(&g_tmp[cum + j]);
                a = __shfl_sync(FULL, a, 0);
                base = twoP + __ldg(&g_aoffL[a]) + __ldg(&g_bpre[a >> 10]);
            }
            float kf = (float)lane;
            for (int k = lane; k < T; k += 32, kf += 32.0f) {
                float val;
                if (k < SEQCAP) val = s_seq[wib][k];
                else {
                    float s = f0;
                    if (k >= s1) s = f1;
                    if (k >= s2) s = f2;
                    if (k >= s3) s = f3;
                    if (k >= s4) s = f4;
                    if (k >= s5) s = f5;
                    if (k >= s6) s = f6;
                    val = s + kf;
                }
                out[base + k] = val;
            }
        }

        // ---- stable order restore: imidx / atidx ----
        long long F = g_F;
        long long imb = F + 3LL * n;
        long long atb = F + 4LL * n;
        for (int j = lane; j < c; j += 32) {
            int vj = (j < ATCAP) ? s_atom[wib][j] : __ldg(&g_tmp[cum + j]);
            int rank = 0;
            for (int k = 0; k < c; ++k) {
                int vk = (k < ATCAP) ? s_atom[wib][k] : __ldg(&g_tmp[cum + k]);
                rank += (vk < vj);
            }
            int slot = cum + rank;
            out[imb + slot] = (float)vj;
            out[atb + vj]   = (float)slot;
        }

        // ---- within-image pairs ----
        if (c < 2) return;
        int npr = c * (c - 1) / 2;
        int off = g_poff[bkt];
        float cumf = (float)cum;
        for (int k = lane; k < npr; k += 32) {
            int pl = (int)((1.0f + sqrtf(8.0f * (float)k + 1.0f)) * 0.5f);
            while (pl * (pl - 1) / 2 > k) --pl;
            while ((pl + 1) * pl / 2 <= k) ++pl;
            int pu = k - pl * (pl - 1) / 2;
            out[off + k]     = cumf + (float)pu;
            out[P + off + k] = cumf + (float)pl;
        }
    } else {
        // ---- frac ----
        int i = (blk - bktb) * 1024 + t;
        if (i >= n) return;
        long long F = g_F;
        float d0 = __ldg(cell + 0), d1 = __ldg(cell + 4), d2 = __ldg(cell + 8);
        out[F + 3LL * i + 0] = __ldg(coord + 3 * i + 0) / d0;
        out[F + 3LL * i + 1] = __ldg(coord + 3 * i + 1) / d1;
        out[F + 3LL * i + 2] = __ldg(coord + 3 * i + 2) / d2;
    }
}

extern "C" void kernel_launch(void* const* d_in, const int* in_sizes, int n_in,
                              void* d_out, int out_size) {
    const float* coord = (const float*)d_in[0];
    const float* cell  = (const float*)d_in[1];
    float* out = (float*)d_out;
    int n = in_sizes[0] / 3;
    int nblk = (n + 1023) / 1024;       // 98

    k_init<<<1, 1024>>>(cell);
    k_bucket<<<nblk, 1024>>>(coord, cell, n);
    k_place<<<nblk, 1024>>>(n, nblk);

    int bktb  = MAXB / 32;              // 256 blocks, warp per bucket
    int tailb = nblk;                   // 98 blocks, frac
    k_emit<<<bktb + tailb, 1024>>>(out, coord, cell, n, bktb);
}

// round 9
// speedup vs baseline: 1.3683x; 1.3683x over previous
#include <cuda_runtime.h>

// CellListComputer: cell-list build, 100k atoms, 20^3 buckets, sm_103a.
// Output layout (float32): [pairs_u | pairs_l | lower_between | frac | imidx | atidx]
// 5 launches:
//   k_init   : zero bucket counters + params
//   k_bucket : bucketize + per-bucket atomic counts; last block: u64 scan -> cum,poff,P
//   k_seq    : warp per bucket: materialize bucket's lower_between sequence into g_seq
//   k_place  : placement via atomicAdd + per-atom neighbor-total scan; last: L,F
//   k_emit   : [warp/atom: copy seq -> out] [bucket warps: sort + pairs + imidx/atidx] [frac]

#define MAXN      100000
#define MAXB      8192
#define MAXCH     104
#define ATCAP     64
#define SEQSTRIDE 512

__device__ int g_grid[3];
__device__ int g_scal[3];
__device__ int g_B;
__device__ int g_P;
__device__ int g_L;
__device__ int g_F;          // 2*P + L (start of frac section)
__device__ unsigned g_done1, g_done2;

__device__ __align__(16) int g_counts[MAXB];
__device__ __align__(16) int g_fill[MAXB];
__device__ __align__(16) int g_cum[MAXB];
__device__ __align__(16) int g_poff[MAXB];
__device__ int g_seqT[MAXB];                 // per-bucket sequence length
__device__ float g_seq[MAXB * SEQSTRIDE];    // per-bucket materialized sequence (16.8MB)
__device__ int g_vec[MAXN];                  // packed vx | vy<<8 | vz<<16
__device__ int g_tmp[MAXN];                  // unordered bucket-sliced atom indices
__device__ int g_aoffL[MAXN];                // block-local exclusive prefix of totals
__device__ int g_bsum[MAXCH];
__device__ int g_bpre[MAXCH];

// inclusive block scan (int), blockDim.x == 1024
__device__ __forceinline__ int blkscan1024(int v, int* wsum) {
    int t = threadIdx.x, lane = t & 31, w = t >> 5;
    #pragma unroll
    for (int o = 1; o < 32; o <<= 1) {
        int x = __shfl_up_sync(0xffffffffu, v, o);
        if (lane >= o) v += x;
    }
    if (lane == 31) wsum[w] = v;
    __syncthreads();
    if (w == 0) {
        int s = wsum[lane];
        #pragma unroll
        for (int o = 1; o < 32; o <<= 1) {
            int x = __shfl_up_sync(0xffffffffu, s, o);
            if (lane >= o) s += x;
        }
        wsum[lane] = s;
    }
    __syncthreads();
    return v + ((w > 0) ? wsum[w - 1] : 0);
}

// inclusive block scan (u64 packed), blockDim.x == 1024
__device__ __forceinline__ unsigned long long
blkscan1024_u64(unsigned long long v, unsigned long long* wsum) {
    int t = threadIdx.x, lane = t & 31, w = t >> 5;
    #pragma unroll
    for (int o = 1; o < 32; o <<= 1) {
        unsigned long long x = __shfl_up_sync(0xffffffffu, v, o);
        if (lane >= o) v += x;
    }
    if (lane == 31) wsum[w] = v;
    __syncthreads();
    if (w == 0) {
        unsigned long long s = wsum[lane];
        #pragma unroll
        for (int o = 1; o < 32; o <<= 1) {
            unsigned long long x = __shfl_up_sync(0xffffffffu, s, o);
            if (lane >= o) s += x;
        }
        wsum[lane] = s;
    }
    __syncthreads();
    return v + ((w > 0) ? wsum[w - 1] : 0ull);
}

__global__ void k_init(const float* __restrict__ cell) {
    int t = threadIdx.x;
    if (t == 0) {
        float bl = (float)(5.2 / 1.0 + 1e-5);
        int g0 = (int)floorf(cell[0] / bl) + 1;
        int g1 = (int)floorf(cell[4] / bl) + 1;
        int g2 = (int)floorf(cell[8] / bl) + 1;
        g_grid[0] = g0; g_grid[1] = g1; g_grid[2] = g2;
        g_B = g0 * g1 * g2;
        g_scal[0] = g1 * g2; g_scal[1] = g1; g_scal[2] = 1;
        g_done1 = 0; g_done2 = 0;
    }
    #pragma unroll
    for (int j = 0; j < MAXB / 1024; ++j) {
        g_counts[j * 1024 + t] = 0;
        g_fill[j * 1024 + t] = 0;
    }
}

// bucketize + count; last-arriving block scans buckets -> g_cum, g_poff, g_P
__global__ void k_bucket(const float* __restrict__ coord,
                         const float* __restrict__ cell, int n) {
    int i = blockIdx.x * 1024 + threadIdx.x;
    if (i < n) {
        float d0 = __ldg(cell + 0), d1 = __ldg(cell + 4), d2 = __ldg(cell + 8);
        float fx = __ldg(coord + 3 * i + 0) / d0;
        float fy = __ldg(coord + 3 * i + 1) / d1;
        float fz = __ldg(coord + 3 * i + 2) / d2;
        int vx = __float2int_rn(fx * (float)(g_grid[0] - 1));
        int vy = __float2int_rn(fy * (float)(g_grid[1] - 1));
        int vz = __float2int_rn(fz * (float)(g_grid[2] - 1));
        int flat = vx * g_scal[0] + vy * g_scal[1] + vz * g_scal[2];
        g_vec[i] = vx | (vy << 8) | (vz << 16);
        atomicAdd(&g_counts[flat], 1);
    }
    __threadfence();
    __syncthreads();
    __shared__ int lastflag;
    if (threadIdx.x == 0)
        lastflag = (atomicAdd(&g_done1, 1) == gridDim.x - 1);
    __syncthreads();
    if (!lastflag) return;

    // ---- bucket scan: counts + pair-counts packed in u64, 8 buckets/thread ----
    __shared__ unsigned long long ws64[32];
    int t = threadIdx.x;
    int cc[8], eC[8], eP[8];
    #pragma unroll
    for (int j = 0; j < 8; ++j) cc[j] = __ldcg(&g_counts[t * 8 + j]);
    int sC = 0, sP = 0;
    #pragma unroll
    for (int j = 0; j < 8; ++j) {
        eC[j] = sC; sC += cc[j];
        eP[j] = sP; sP += cc[j] * (cc[j] - 1) / 2;
    }
    unsigned long long v = ((unsigned long long)(unsigned)sC << 32) | (unsigned)sP;
    unsigned long long incl = blkscan1024_u64(v, ws64);
    unsigned long long excl = incl - v;
    int baseC = (int)(excl >> 32);
    int baseP = (int)(excl & 0xffffffffull);
    int4 oc0 = make_int4(baseC + eC[0], baseC + eC[1], baseC + eC[2], baseC + eC[3]);
    int4 oc1 = make_int4(baseC + eC[4], baseC + eC[5], baseC + eC[6], baseC + eC[7]);
    int4 op0 = make_int4(baseP + eP[0], baseP + eP[1], baseP + eP[2], baseP + eP[3]);
    int4 op1 = make_int4(baseP + eP[4], baseP + eP[5], baseP + eP[6], baseP + eP[7]);
    *reinterpret_cast<int4*>(&g_cum[t * 8])      = oc0;
    *reinterpret_cast<int4*>(&g_cum[t * 8 + 4])  = oc1;
    *reinterpret_cast<int4*>(&g_poff[t * 8])     = op0;
    *reinterpret_cast<int4*>(&g_poff[t * 8 + 4]) = op1;
    if (t == 1023) g_P = (int)(incl & 0xffffffffull);
}

// warp per bucket: materialize lower_between sequence for this bucket
__global__ void k_seq() {
    const unsigned FULL = 0xffffffffu;
    int t = threadIdx.x, wib = t >> 5, lane = t & 31;
    int bkt = blockIdx.x * 32 + wib;
    if (bkt >= g_B) return;

    int cnt_d = 0, cum_d = 0;
    if (lane < 7) {
        int s0 = g_scal[0], s1g = g_scal[1];
        int g0 = g_grid[0], g1 = g_grid[1], g2 = g_grid[2];
        int vx = bkt / s0; int r = bkt - vx * s0;
        int vy = r / s1g;  int vz = r - vy * s1g;
        int dx = (lane >> 2) - 1;
        int dy = ((lane >> 1) & 1) - 1;
        int dz = (lane & 1) - 1;
        int nx = vx + dx; if (nx < 0) nx += g0;
        int ny = vy + dy; if (ny < 0) ny += g1;
        int nz = vz + dz; if (nz < 0) nz += g2;
        int nb = nx * s0 + ny * s1g + nz;
        cnt_d = g_counts[nb];
        cum_d = g_cum[nb];
    }
    int sc = cnt_d;
    #pragma unroll
    for (int o = 1; o < 8; o <<= 1) {
        int x = __shfl_up_sync(FULL, sc, o);
        if (lane >= o) sc += x;
    }
    int st = sc - cnt_d;
    float fseg = (float)(cum_d - st);
    int T = __shfl_sync(FULL, sc, 6);
    if (T > SEQSTRIDE) T = SEQSTRIDE;   // capacity guard (T ~ 87 expected)

    float f0 = __shfl_sync(FULL, fseg, 0);
    int   s1 = __shfl_sync(FULL, st, 1); float f1 = __shfl_sync(FULL, fseg, 1);
    int   s2 = __shfl_sync(FULL, st, 2); float f2 = __shfl_sync(FULL, fseg, 2);
    int   s3 = __shfl_sync(FULL, st, 3); float f3 = __shfl_sync(FULL, fseg, 3);
    int   s4 = __shfl_sync(FULL, st, 4); float f4 = __shfl_sync(FULL, fseg, 4);
    int   s5 = __shfl_sync(FULL, st, 5); float f5 = __shfl_sync(FULL, fseg, 5);
    int   s6 = __shfl_sync(FULL, st, 6); float f6 = __shfl_sync(FULL, fseg, 6);

    float* sp = &g_seq[(long long)bkt * SEQSTRIDE];
    float kf = (float)lane;
    for (int k = lane; k < T; k += 32, kf += 32.0f) {
        float s = f0;
        if (k >= s1) s = f1;
        if (k >= s2) s = f2;
        if (k >= s3) s = f3;
        if (k >= s4) s = f4;
        if (k >= s5) s = f5;
        if (k >= s6) s = f6;
        sp[k] = s + kf;
    }
    if (lane == 0) g_seqT[bkt] = T;
}

// unordered placement + per-atom neighbor totals; last block: L, F, bpre
__global__ void k_place(int n, int nch) {
    __shared__ int ws[32];
    int t = threadIdx.x;
    int i = blockIdx.x * 1024 + t;
    bool valid = (i < n);
    int tsum = 0;
    if (valid) {
        int pk = g_vec[i];
        int vx = pk & 0xFF, vy = (pk >> 8) & 0xFF, vz = (pk >> 16) & 0xFF;
        int g0 = g_grid[0], g1 = g_grid[1], g2 = g_grid[2];
        int s0 = g_scal[0], s1 = g_scal[1];
        int flat = vx * s0 + vy * s1 + vz;
        int slot = g_cum[flat] + atomicAdd(&g_fill[flat], 1);
        g_tmp[slot] = i;
        #pragma unroll
        for (int d = 0; d < 7; ++d) {
            int dx = (d >> 2) - 1;
            int dy = ((d >> 1) & 1) - 1;
            int dz = (d & 1) - 1;
            int nx = vx + dx; if (nx < 0) nx += g0;
            int ny = vy + dy; if (ny < 0) ny += g1;
            int nz = vz + dz; if (nz < 0) nz += g2;
            tsum += g_counts[nx * s0 + ny * s1 + nz];
        }
    }
    int incl = blkscan1024(tsum, ws);
    if (valid) g_aoffL[i] = incl - tsum;
    if (t == 1023) g_bsum[blockIdx.x] = incl;

    __threadfence();
    __syncthreads();
    __shared__ int lastflag;
    if (t == 0) lastflag = (atomicAdd(&g_done2, 1) == gridDim.x - 1);
    __syncthreads();
    if (!lastflag) return;

    if (t < 32) {
        int ex[4];
        int s = 0;
        #pragma unroll
        for (int j = 0; j < 4; ++j) {
            int idx = t * 4 + j;
            int x = (idx < nch) ? __ldcg(&g_bsum[idx]) : 0;
            ex[j] = s; s += x;
        }
        int iw = s;
        #pragma unroll
        for (int o = 1; o < 32; o <<= 1) {
            int x = __shfl_up_sync(0xffffffffu, iw, o);
            if (t >= o) iw += x;
        }
        int base = iw - s;
        #pragma unroll
        for (int j = 0; j < 4; ++j) {
            int idx = t * 4 + j;
            if (idx < nch) g_bpre[idx] = base + ex[j];
        }
        if (t == 31) { g_L = iw; g_F = 2 * g_P + iw; }
    }
}

// Fused output writer.
//  [0,fillb): warp per atom — copy bucket sequence to atom's slice
//  [fillb,fillb+bktb): warp per bucket — rank-sort (imidx/atidx) + pairs
//  rest: frac
__global__ void k_emit(float* __restrict__ out,
                       const float* __restrict__ coord,
                       const float* __restrict__ cell,
                       int n, int fillb, int bktb) {
    const unsigned FULL = 0xffffffffu;
    int blk = blockIdx.x;
    int t = threadIdx.x;
    if (blk < fillb) {
        // ---- lower_between: warp per atom, pure copy from materialized seq ----
        int wib = t >> 5, lane = t & 31;
        int w = blk * 32 + wib;
        if (w >= n) return;
        int flat = 0, base = 0, T = 0;
        if (lane == 0) {
            int pk = g_vec[w];
            int vx = pk & 0xFF, vy = (pk >> 8) & 0xFF, vz = (pk >> 16) & 0xFF;
            flat = vx * g_scal[0] + vy * g_scal[1] + vz;
            base = 2 * g_P + g_aoffL[w] + g_bpre[w >> 10];
            T = g_seqT[flat];
        }
        flat = __shfl_sync(FULL, flat, 0);
        base = __shfl_sync(FULL, base, 0);
        T    = __shfl_sync(FULL, T, 0);
        const float* sp = &g_seq[(long long)flat * SEQSTRIDE];
        for (int k = lane; k < T; k += 32)
            out[base + k] = __ldg(&sp[k]);
    } else if (blk < fillb + bktb) {
        // ---- warp per bucket: stable order restore + pairs ----
        __shared__ int s_atom[32][ATCAP];
        int wib = t >> 5, lane = t & 31;
        int bkt = (blk - fillb) * 32 + wib;
        if (bkt >= g_B) return;
        int c = g_counts[bkt];
        if (c == 0) return;
        int cum = g_cum[bkt];
        long long F = g_F;
        long long imb = F + 3LL * n;
        long long atb = F + 4LL * n;
        int cl = (c < ATCAP) ? c : ATCAP;
        for (int j = lane; j < cl; j += 32)
            s_atom[wib][j] = g_tmp[cum + j];
        __syncwarp();
        for (int j = lane; j < c; j += 32) {
            int vj = (j < ATCAP) ? s_atom[wib][j] : __ldg(&g_tmp[cum + j]);
            int rank = 0;
            for (int k = 0; k < c; ++k) {
                int vk = (k < ATCAP) ? s_atom[wib][k] : __ldg(&g_tmp[cum + k]);
                rank += (vk < vj);
            }
            int slot = cum + rank;
            out[imb + slot] = (float)vj;
            out[atb + vj]   = (float)slot;
        }
        if (c < 2) return;
        int npr = c * (c - 1) / 2;
        int off = g_poff[bkt];
        int P = g_P;
        float cumf = (float)cum;
        for (int k = lane; k < npr; k += 32) {
            int pl = (int)((1.0f + sqrtf(8.0f * (float)k + 1.0f)) * 0.5f);
            while (pl * (pl - 1) / 2 > k) --pl;
            while ((pl + 1) * pl / 2 <= k) ++pl;
            int pu = k - pl * (pl - 1) / 2;
            out[off + k]     = cumf + (float)pu;
            out[P + off + k] = cumf + (float)pl;
        }
    } else {
        // ---- frac ----
        int i = (blk - fillb - bktb) * 1024 + t;
        if (i >= n) return;
        long long F = g_F;
        float d0 = __ldg(cell + 0), d1 = __ldg(cell + 4), d2 = __ldg(cell + 8);
        out[F + 3LL * i + 0] = __ldg(coord + 3 * i + 0) / d0;
        out[F + 3LL * i + 1] = __ldg(coord + 3 * i + 1) / d1;
        out[F + 3LL * i + 2] = __ldg(coord + 3 * i + 2) / d2;
    }
}

extern "C" void kernel_launch(void* const* d_in, const int* in_sizes, int n_in,
                              void* d_out, int out_size) {
    const float* coord = (const float*)d_in[0];
    const float* cell  = (const float*)d_in[1];
    float* out = (float*)d_out;
    int n = in_sizes[0] / 3;
    int nblk = (n + 1023) / 1024;       // 98

    k_init<<<1, 1024>>>(cell);
    k_bucket<<<nblk, 1024>>>(coord, cell, n);
    k_seq<<<MAXB / 32, 1024>>>();
    k_place<<<nblk, 1024>>>(n, nblk);

    int fillb = (n + 31) / 32;          // 3125 blocks, warp per atom
    int bktb  = MAXB / 32;              // 256 blocks, warp per bucket
    int tailb = nblk;                   // 98 blocks, frac
    k_emit<<<fillb + bktb + tailb, 1024>>>(out, coord, cell, n, fillb, bktb);
}